// round 10
// baseline (speedup 1.0000x reference)
#include <cuda_runtime.h>
#include <cuda_bf16.h>
#include <cstdint>

// Off-diagonal Gram sum via:
//   (1/D) sum_d [ (sum_b x2[b,d])^2 - sum_b x2[b,d]^2 ],  x2 = x*x.
//
// R10: R9 structure (294 CTAs x 512 thr, warp-internal 4-way b-split,
// 8 staged LDG.128/thread, f32x2 math) + compile-time-constant strides
// (shape is fixed: D=150528, d4=37632) so every load is LDG [Rbase+imm]
// with no IMAD address chain, + slimmer cross-warp epilogue.
// Generic fallback kernel guards against any shape change.

#define B_ROWS 32
#define THREADS 512
#define QROWS 8
#define D4_CONST 37632          // 150528 / 4

__device__ double g_acc = 0.0;
__device__ unsigned int g_count = 0;

__device__ __forceinline__ unsigned long long pk2(float lo, float hi) {
    unsigned long long r;
    asm("mov.b64 %0, {%1, %2};" : "=l"(r) : "f"(lo), "f"(hi));
    return r;
}
__device__ __forceinline__ void upk2(unsigned long long v, float& lo, float& hi) {
    asm("mov.b64 {%0, %1}, %2;" : "=f"(lo), "=f"(hi) : "l"(v));
}
__device__ __forceinline__ unsigned long long mul2(unsigned long long a, unsigned long long b) {
    unsigned long long r;
    asm("mul.rn.f32x2 %0, %1, %2;" : "=l"(r) : "l"(a), "l"(b));
    return r;
}
__device__ __forceinline__ unsigned long long add2(unsigned long long a, unsigned long long b) {
    unsigned long long r;
    asm("add.rn.f32x2 %0, %1, %2;" : "=l"(r) : "l"(a), "l"(b));
    return r;
}
__device__ __forceinline__ unsigned long long fma2(unsigned long long a, unsigned long long b,
                                                   unsigned long long c) {
    unsigned long long r;
    asm("fma.rn.f32x2 %0, %1, %2, %3;" : "=l"(r) : "l"(a), "l"(b), "l"(c));
    return r;
}

template <int D4>
__device__ __forceinline__ void ortho_body(const float4* __restrict__ in,
                                           float* __restrict__ out,
                                           double inv_d, int nblocks) {
    const int tid  = threadIdx.x;
    const int lane = tid & 31;
    const int q    = lane >> 3;                       // b-quarter 0..3
    const int c    = lane & 7;                        // column within warp
    const int wid  = tid >> 5;
    const int gw   = blockIdx.x * (THREADS / 32) + wid;
    const int col  = gw * 8 + c;

    // 8 staged loads at compile-time-constant offsets from one base
    const float4* p = in + (size_t)(q * QROWS) * D4 + col;
    float4 v[QROWS];
    #pragma unroll
    for (int j = 0; j < QROWS; j++)
        v[j] = p[(size_t)j * D4];

    unsigned long long s01 = 0ull, s23 = 0ull, t01 = 0ull, t23 = 0ull;
    #pragma unroll
    for (int j = 0; j < QROWS; j++) {
        unsigned long long v01 = pk2(v[j].x, v[j].y);
        unsigned long long v23 = pk2(v[j].z, v[j].w);
        unsigned long long a01 = mul2(v01, v01);
        unsigned long long a23 = mul2(v23, v23);
        s01 = add2(s01, a01);
        s23 = add2(s23, a23);
        t01 = fma2(a01, a01, t01);
        t23 = fma2(a23, a23, t23);
    }

    float sx, sy, sz, sw, tx, ty, tz, tw;
    upk2(s01, sx, sy); upk2(s23, sz, sw);
    upk2(t01, tx, ty); upk2(t23, tz, tw);
    float tsum = (tx + ty) + (tz + tw);

    // recombine s across the 4 b-quarters (lanes c, c+8, c+16, c+24)
    sx += __shfl_xor_sync(0xFFFFFFFFu, sx, 8);
    sx += __shfl_xor_sync(0xFFFFFFFFu, sx, 16);
    sy += __shfl_xor_sync(0xFFFFFFFFu, sy, 8);
    sy += __shfl_xor_sync(0xFFFFFFFFu, sy, 16);
    sz += __shfl_xor_sync(0xFFFFFFFFu, sz, 8);
    sz += __shfl_xor_sync(0xFFFFFFFFu, sz, 16);
    sw += __shfl_xor_sync(0xFFFFFFFFu, sw, 8);
    sw += __shfl_xor_sync(0xFFFFFFFFu, sw, 16);

    float val = -tsum;
    if (q == 0)
        val += (sx * sx + sy * sy) + (sz * sz + sw * sw);

    #pragma unroll
    for (int off = 16; off > 0; off >>= 1)
        val += __shfl_xor_sync(0xFFFFFFFFu, val, off);

    __shared__ float warp_sums[THREADS / 32];
    if (lane == 0) warp_sums[wid] = val;
    __syncthreads();

    // warp 0 finishes: 16 partials -> lane-parallel shfl tree -> one atomic
    if (wid == 0) {
        float blk = (lane < THREADS / 32) ? warp_sums[lane] : 0.f;
        #pragma unroll
        for (int off = 8; off > 0; off >>= 1)
            blk += __shfl_xor_sync(0xFFFFFFFFu, blk, off);
        if (lane == 0) {
            atomicAdd(&g_acc, (double)blk);
            __threadfence();
            unsigned int ticket = atomicAdd(&g_count, 1u);
            if (ticket == (unsigned int)nblocks - 1u) {
                out[0] = (float)(g_acc * inv_d);
                g_acc = 0.0;     // reset for next graph replay
                g_count = 0u;
            }
        }
    }
}

__global__ void __launch_bounds__(THREADS, 2)
ortho_fixed_kernel(const float4* __restrict__ in, float* __restrict__ out,
                   double inv_d, int nblocks) {
    ortho_body<D4_CONST>(in, out, inv_d, nblocks);
}

// Generic fallback (runtime d4), identical math, simple per-thread column loop.
__global__ void __launch_bounds__(256, 1)
ortho_generic_kernel(const float4* __restrict__ in, float* __restrict__ out,
                     int d4, double inv_d, int nblocks) {
    int idx = blockIdx.x * 256 + threadIdx.x;
    float s0 = 0.f, s1 = 0.f, s2 = 0.f, s3 = 0.f;
    float t0 = 0.f, t1 = 0.f, t2 = 0.f, t3 = 0.f;
    if (idx < d4) {
        #pragma unroll
        for (int b = 0; b < B_ROWS; b++) {
            float4 v = in[(size_t)b * d4 + idx];
            float a0 = v.x * v.x, a1 = v.y * v.y, a2 = v.z * v.z, a3 = v.w * v.w;
            s0 += a0; t0 = fmaf(a0, a0, t0);
            s1 += a1; t1 = fmaf(a1, a1, t1);
            s2 += a2; t2 = fmaf(a2, a2, t2);
            s3 += a3; t3 = fmaf(a3, a3, t3);
        }
    }
    float val = (fmaf(s0, s0, -t0) + fmaf(s1, s1, -t1))
              + (fmaf(s2, s2, -t2) + fmaf(s3, s3, -t3));
    #pragma unroll
    for (int off = 16; off > 0; off >>= 1)
        val += __shfl_xor_sync(0xFFFFFFFFu, val, off);
    __shared__ float ws[8];
    int lane = threadIdx.x & 31, wid = threadIdx.x >> 5;
    if (lane == 0) ws[wid] = val;
    __syncthreads();
    if (wid == 0) {
        float blk = (lane < 8) ? ws[lane] : 0.f;
        #pragma unroll
        for (int off = 4; off > 0; off >>= 1)
            blk += __shfl_xor_sync(0xFFFFFFFFu, blk, off);
        if (lane == 0) {
            atomicAdd(&g_acc, (double)blk);
            __threadfence();
            unsigned int ticket = atomicAdd(&g_count, 1u);
            if (ticket == (unsigned int)nblocks - 1u) {
                out[0] = (float)(g_acc * inv_d);
                g_acc = 0.0;
                g_count = 0u;
            }
        }
    }
}

extern "C" void kernel_launch(void* const* d_in, const int* in_sizes, int n_in,
                              void* d_out, int out_size) {
    const float4* in = (const float4*)d_in[0];
    float* out = (float*)d_out;

    int total = in_sizes[0];
    int D = total / B_ROWS;
    int d4 = D / 4;

    if (d4 == D4_CONST) {
        int blocks = D4_CONST / ((THREADS / 32) * 8);   // 294, exact
        ortho_fixed_kernel<<<blocks, THREADS>>>(in, out, 1.0 / (double)D, blocks);
    } else {
        int blocks = (d4 + 255) / 256;
        ortho_generic_kernel<<<blocks, 256>>>(in, out, d4, 1.0 / (double)D, blocks);
    }
}